// round 14
// baseline (speedup 1.0000x reference)
#include <cuda_runtime.h>
#include <cuda_bf16.h>
#include <cstdint>
#include <math.h>

#define NMAX 50016
#define EMAX 800032

// ---------------- scratch (device globals; no runtime allocation) ------------
__device__ float g_q[NMAX * 128];
__device__ float g_k[NMAX * 128];
__device__ float g_v[NMAX * 128];
__device__ float g_r[NMAX * 128];
__device__ float g_o[NMAX * 128];
__device__ float g_e[(size_t)EMAX * 128];
__device__ float g_escore[EMAX * 8];
__device__ __nv_bfloat16 g_wt[7 * 2 * 16384];   // [slot][hi/lo][n*128+k]
__device__ __nv_bfloat16 g_xh[NMAX * 128];
__device__ __nv_bfloat16 g_xl[NMAX * 128];
__device__ int   g_counts[NMAX + 8];
__device__ int   g_off[NMAX + 8];
__device__ int   g_cursor[NMAX + 8];
__device__ int   g_elist[EMAX];
__device__ int   g_bsum[64];

__device__ __forceinline__ uint32_t smem_u32(const void* p) {
    uint32_t a;
    asm("{ .reg .u64 t; cvta.to.shared.u64 t, %1; cvt.u32.u64 %0, t; }" : "=r"(a) : "l"(p));
    return a;
}
__device__ __forceinline__ void ldsm4(uint32_t* r, uint32_t addr) {
    asm volatile("ldmatrix.sync.aligned.m8n8.x4.shared.b16 {%0,%1,%2,%3}, [%4];"
        : "=r"(r[0]), "=r"(r[1]), "=r"(r[2]), "=r"(r[3]) : "r"(addr));
}
__device__ __forceinline__ uint32_t cvt2(float x, float y) {
    uint32_t d;
    asm("cvt.rn.bf16x2.f32 %0, %1, %2;" : "=r"(d) : "f"(y), "f"(x));
    return d;
}
__device__ __forceinline__ void mma16816(float* c, const uint32_t* a, uint32_t b0, uint32_t b1) {
    asm volatile("mma.sync.aligned.m16n8k16.row.col.f32.bf16.bf16.f32 "
        "{%0,%1,%2,%3}, {%4,%5,%6,%7}, {%8,%9}, {%0,%1,%2,%3};"
        : "+f"(c[0]), "+f"(c[1]), "+f"(c[2]), "+f"(c[3])
        : "r"(a[0]), "r"(a[1]), "r"(a[2]), "r"(a[3]), "r"(b0), "r"(b1));
}
__device__ __forceinline__ void cp_async16(uint32_t dst, const void* src) {
    asm volatile("cp.async.cg.shared.global [%0], [%1], 16;" :: "r"(dst), "l"(src));
}
#define CP_COMMIT() asm volatile("cp.async.commit_group;" ::: "memory")
#define CP_WAIT0()  asm volatile("cp.async.wait_group 0;" ::: "memory")

// ---------------- shared tile constants ---------------------------------------
#define APAD 136
#define MT_STRIDE (16 * APAD * 2)

// === framework A: BM=64, 256 thr, warp 32x32 (qkvr_gemm / gate_ln) ============
#define A_BYTES (64 * APAD * 2)
#define B_BYTES (128 * APAD * 2)
#define SMEM_G (2 * A_BYTES + 2 * B_BYTES)      // 104448
#define OFF_AH 0
#define OFF_AL A_BYTES
#define OFF_BH (2 * A_BYTES)
#define OFF_BL (2 * A_BYTES + B_BYTES)

__device__ __forceinline__ void fill_A_f32(char* sm, const float* Ag, int m0, int M, int tid) {
#pragma unroll
    for (int i = 0; i < 8; ++i) {
        int t4 = tid + i * 256;
        int m = t4 >> 5, c4 = t4 & 31;
        float4 v = make_float4(0.f, 0.f, 0.f, 0.f);
        if (m0 + m < M) v = *(const float4*)&Ag[(size_t)(m0 + m) * 128 + (c4 << 2)];
        uint32_t hp0 = cvt2(v.x, v.y), hp1 = cvt2(v.z, v.w);
        float lx = v.x - __uint_as_float(hp0 << 16);
        float ly = v.y - __uint_as_float(hp0 & 0xFFFF0000u);
        float lz = v.z - __uint_as_float(hp1 << 16);
        float lw = v.w - __uint_as_float(hp1 & 0xFFFF0000u);
        int boff = (m * APAD + (c4 << 2)) * 2;
        *(uint2*)(sm + OFF_AH + boff) = make_uint2(hp0, hp1);
        *(uint2*)(sm + OFF_AL + boff) = make_uint2(cvt2(lx, ly), cvt2(lz, lw));
    }
}
__device__ __forceinline__ void fill_A_bf16(char* sm, const __nv_bfloat16* Agh,
                                            const __nv_bfloat16* Agl, int m0, int M, int tid) {
#pragma unroll
    for (int i = 0; i < 4; ++i) {
        int t = tid + i * 256;
        int m = t >> 4, c8 = (t & 15) << 3;
        uint4 vh = make_uint4(0, 0, 0, 0), vl = make_uint4(0, 0, 0, 0);
        if (m0 + m < M) {
            vh = *(const uint4*)&Agh[(size_t)(m0 + m) * 128 + c8];
            vl = *(const uint4*)&Agl[(size_t)(m0 + m) * 128 + c8];
        }
        int boff = (m * APAD + c8) * 2;
        *(uint4*)(sm + OFF_AH + boff) = vh;
        *(uint4*)(sm + OFF_AL + boff) = vl;
    }
}
__device__ __forceinline__ void fill_B(char* sm, const __nv_bfloat16* Wth,
                                       const __nv_bfloat16* Wtl, int tid) {
#pragma unroll
    for (int i = 0; i < 8; ++i) {
        int t = tid + i * 256;
        int n = t >> 4, k8 = (t & 15) << 3;
        int boff = (n * APAD + k8) * 2;
        *(uint4*)(sm + OFF_BH + boff) = *(const uint4*)&Wth[n * 128 + k8];
        *(uint4*)(sm + OFF_BL + boff) = *(const uint4*)&Wtl[n * 128 + k8];
    }
}
__device__ __forceinline__ void mma_tile(uint32_t smb, uint32_t a_off, uint32_t b_off,
                                         float acc[2][4][4]) {
    const uint32_t AHs = smb + OFF_AH, ALs = smb + OFF_AL;
    const uint32_t BHs = smb + OFF_BH, BLs = smb + OFF_BL;
#pragma unroll
    for (int ks = 0; ks < 8; ++ks) {
        const uint32_t kb = ks * 32;
        uint32_t ah[2][4], al[2][4], bh[2][4], bl[2][4];
#pragma unroll
        for (int mt = 0; mt < 2; ++mt) {
            ldsm4(ah[mt], AHs + a_off + mt * MT_STRIDE + kb);
            ldsm4(al[mt], ALs + a_off + mt * MT_STRIDE + kb);
        }
#pragma unroll
        for (int p = 0; p < 2; ++p) {
            ldsm4(bh[p], BHs + b_off + p * MT_STRIDE + kb);
            ldsm4(bl[p], BLs + b_off + p * MT_STRIDE + kb);
        }
#pragma unroll
        for (int mt = 0; mt < 2; ++mt)
#pragma unroll
            for (int nt = 0; nt < 4; ++nt) {
                uint32_t b0h = bh[nt >> 1][(nt & 1) * 2], b1h = bh[nt >> 1][(nt & 1) * 2 + 1];
                uint32_t b0l = bl[nt >> 1][(nt & 1) * 2], b1l = bl[nt >> 1][(nt & 1) * 2 + 1];
                mma16816(acc[mt][nt], ah[mt], b0h, b1h);
                mma16816(acc[mt][nt], al[mt], b0h, b1h);
                mma16816(acc[mt][nt], ah[mt], b0l, b1l);
            }
    }
}
#define CLEAR_ACC(acc) \
    _Pragma("unroll") for (int _a = 0; _a < 2; ++_a) \
    _Pragma("unroll") for (int _b = 0; _b < 4; ++_b) \
    _Pragma("unroll") for (int _c = 0; _c < 4; ++_c) acc[_a][_b][_c] = 0.f;

// === framework B: persistent BM=128, double-buffered A, pipelined convert =====
#define A2_BYTES (128 * APAD * 2)               // 34816
#define E_BH (4 * A2_BYTES)
#define E_BL (5 * A2_BYTES)
#define SMEM_EP (6 * A2_BYTES)                  // 208896

__device__ __forceinline__ void conv_store(char* sm, uint32_t ah_base_off, uint32_t al_base_off,
                                           int chunk, int tid, const float4& v0, const float4& v1) {
    int c = tid + chunk * 256;
    int m = c >> 4, col8 = (c & 15) << 3;
    uint32_t h0 = cvt2(v0.x, v0.y), h1 = cvt2(v0.z, v0.w);
    uint32_t h2 = cvt2(v1.x, v1.y), h3 = cvt2(v1.z, v1.w);
    float l0x = v0.x - __uint_as_float(h0 << 16);
    float l0y = v0.y - __uint_as_float(h0 & 0xFFFF0000u);
    float l0z = v0.z - __uint_as_float(h1 << 16);
    float l0w = v0.w - __uint_as_float(h1 & 0xFFFF0000u);
    float l1x = v1.x - __uint_as_float(h2 << 16);
    float l1y = v1.y - __uint_as_float(h2 & 0xFFFF0000u);
    float l1z = v1.z - __uint_as_float(h3 << 16);
    float l1w = v1.w - __uint_as_float(h3 & 0xFFFF0000u);
    int boff = (m * APAD + col8) * 2;
    *(uint4*)(sm + ah_base_off + boff) = make_uint4(h0, h1, h2, h3);
    *(uint4*)(sm + al_base_off + boff) = make_uint4(cvt2(l0x, l0y), cvt2(l0z, l0w),
                                                    cvt2(l1x, l1y), cvt2(l1z, l1w));
}

__global__ __launch_bounds__(256, 1)
void tc_gemm(const float* __restrict__ A,
             const __nv_bfloat16* __restrict__ Wt_h, const __nv_bfloat16* __restrict__ Wt_l,
             const float* __restrict__ bias, float* __restrict__ C, int M)
{
    extern __shared__ char sm[];
    const int tid = threadIdx.x, wid = tid >> 5, lane = tid & 31;
    const int wm = (wid >> 2) * 64, wn = (wid & 3) * 32;
    const int group = lane >> 2, tig = lane & 3;
    const uint32_t smb = smem_u32(sm);
    const int numTiles = (M + 127) >> 7;

#pragma unroll
    for (int i = 0; i < 8; ++i) {
        int t = tid + i * 256;
        int n = t >> 4, k8 = (t & 15) << 3;
        uint32_t boff = (uint32_t)(n * APAD + k8) * 2;
        cp_async16(smb + E_BH + boff, &Wt_h[n * 128 + k8]);
        cp_async16(smb + E_BL + boff, &Wt_l[n * 128 + k8]);
    }
    CP_COMMIT();

    if ((int)blockIdx.x < numTiles) {
        int m0 = blockIdx.x * 128;
#pragma unroll
        for (int i = 0; i < 8; ++i) {
            int c = tid + i * 256;
            int m = c >> 4, col8 = (c & 15) << 3;
            float4 v0 = make_float4(0.f, 0.f, 0.f, 0.f), v1 = v0;
            if (m0 + m < M) {
                v0 = *(const float4*)&A[(size_t)(m0 + m) * 128 + col8];
                v1 = *(const float4*)&A[(size_t)(m0 + m) * 128 + col8 + 4];
            }
            conv_store(sm, 0, A2_BYTES, i, tid, v0, v1);
        }
    }
    CP_WAIT0();
    __syncthreads();

    const uint32_t BHs = smb + E_BH, BLs = smb + E_BL;
    const uint32_t a_off = ((wm + (lane & 15)) * APAD + ((lane >> 4) << 3)) * 2;
    const uint32_t b_off = ((wn + ((lane >> 4) << 3) + (lane & 7)) * APAD + (((lane >> 3) & 1) << 3)) * 2;

    int buf = 0;
    for (int t = blockIdx.x; t < numTiles; t += gridDim.x) {
        const int m0 = t * 128;
        const int tn = t + gridDim.x;
        const bool hasNext = (tn < numTiles);
        const int m0n = tn * 128;
        const uint32_t AHs = smb + (uint32_t)buf * 2 * A2_BYTES;
        const uint32_t ALs = AHs + A2_BYTES;
        const uint32_t ah_n = (uint32_t)(buf ^ 1) * 2 * A2_BYTES;
        const uint32_t al_n = ah_n + A2_BYTES;

        float acc[4][4][4];
#pragma unroll
        for (int a = 0; a < 4; ++a)
#pragma unroll
            for (int b = 0; b < 4; ++b)
#pragma unroll
                for (int c = 0; c < 4; ++c) acc[a][b][c] = 0.f;

        float4 pv[2][2];

#pragma unroll
        for (int ks = 0; ks < 8; ++ks) {
            if (hasNext && ks >= 2)
                conv_store(sm, ah_n, al_n, ks - 2, tid, pv[ks & 1][0], pv[ks & 1][1]);
            if (hasNext) {
                int c = tid + ks * 256;
                int m = c >> 4, col8 = (c & 15) << 3;
                if (m0n + m < M) {
                    pv[ks & 1][0] = *(const float4*)&A[(size_t)(m0n + m) * 128 + col8];
                    pv[ks & 1][1] = *(const float4*)&A[(size_t)(m0n + m) * 128 + col8 + 4];
                } else {
                    pv[ks & 1][0] = make_float4(0.f, 0.f, 0.f, 0.f);
                    pv[ks & 1][1] = make_float4(0.f, 0.f, 0.f, 0.f);
                }
            }
            const uint32_t kb = ks * 32;
            uint32_t ah[4][4], al[4][4], bh[2][4], bl[2][4];
#pragma unroll
            for (int mt = 0; mt < 4; ++mt) {
                ldsm4(ah[mt], AHs + a_off + mt * MT_STRIDE + kb);
                ldsm4(al[mt], ALs + a_off + mt * MT_STRIDE + kb);
            }
#pragma unroll
            for (int p = 0; p < 2; ++p) {
                ldsm4(bh[p], BHs + b_off + p * MT_STRIDE + kb);
                ldsm4(bl[p], BLs + b_off + p * MT_STRIDE + kb);
            }
#pragma unroll
            for (int mt = 0; mt < 4; ++mt)
#pragma unroll
                for (int nt = 0; nt < 4; ++nt) {
                    uint32_t b0h = bh[nt >> 1][(nt & 1) * 2], b1h = bh[nt >> 1][(nt & 1) * 2 + 1];
                    uint32_t b0l = bl[nt >> 1][(nt & 1) * 2], b1l = bl[nt >> 1][(nt & 1) * 2 + 1];
                    mma16816(acc[mt][nt], ah[mt], b0h, b1h);
                    mma16816(acc[mt][nt], al[mt], b0h, b1h);
                    mma16816(acc[mt][nt], ah[mt], b0l, b1l);
                }
        }
        if (hasNext) {
            conv_store(sm, ah_n, al_n, 6, tid, pv[0][0], pv[0][1]);
            conv_store(sm, ah_n, al_n, 7, tid, pv[1][0], pv[1][1]);
        }

#pragma unroll
        for (int mt = 0; mt < 4; ++mt) {
            int r0 = m0 + wm + mt * 16 + group, r1 = r0 + 8;
#pragma unroll
            for (int nt = 0; nt < 4; ++nt) {
                int col = wn + nt * 8 + tig * 2;
                float2 bb = *(const float2*)&bias[col];
                if (r0 < M) *(float2*)&C[(size_t)r0 * 128 + col] =
                    make_float2(acc[mt][nt][0] + bb.x, acc[mt][nt][1] + bb.y);
                if (r1 < M) *(float2*)&C[(size_t)r1 * 128 + col] =
                    make_float2(acc[mt][nt][2] + bb.x, acc[mt][nt][3] + bb.y);
            }
        }
        __syncthreads();
        buf ^= 1;
    }
}

// ---------------- fused QKVR: 4 GEMMs sharing one A tile ----------------------
__global__ __launch_bounds__(256, 2)
void qkvr_gemm(const __nv_bfloat16* __restrict__ xh, const __nv_bfloat16* __restrict__ xl,
               const __nv_bfloat16* __restrict__ wt,
               const float* __restrict__ bq, const float* __restrict__ bk,
               const float* __restrict__ bv, const float* __restrict__ br,
               float* __restrict__ q, float* __restrict__ k,
               float* __restrict__ v, float* __restrict__ r, int M)
{
    extern __shared__ char sm[];
    const int tid = threadIdx.x, wid = tid >> 5, lane = tid & 31;
    const int m0 = blockIdx.x * 64;
    const int wm = (wid >> 2) * 32, wn = (wid & 3) * 32;
    const int group = lane >> 2, tig = lane & 3;

    fill_A_bf16(sm, xh, xl, m0, M, tid);

    const uint32_t smb = smem_u32(sm);
    const uint32_t a_off = ((wm + (lane & 15)) * APAD + ((lane >> 4) << 3)) * 2;
    const uint32_t b_off = ((wn + ((lane >> 4) << 3) + (lane & 7)) * APAD + (((lane >> 3) & 1) << 3)) * 2;

    const float* bs[4] = {bq, bk, bv, br};
    float* outs[4] = {q, k, v, r};

#pragma unroll
    for (int w = 0; w < 4; ++w) {
        fill_B(sm, wt + w * 32768, wt + w * 32768 + 16384, tid);
        __syncthreads();

        float acc[2][4][4];
        CLEAR_ACC(acc);
        mma_tile(smb, a_off, b_off, acc);

        const float* bias = bs[w];
        float* C = outs[w];
#pragma unroll
        for (int mt = 0; mt < 2; ++mt) {
            int r0 = m0 + wm + mt * 16 + group, r1 = r0 + 8;
#pragma unroll
            for (int nt = 0; nt < 4; ++nt) {
                int col = wn + nt * 8 + tig * 2;
                float2 bb = *(const float2*)&bias[col];
                if (r0 < M) *(float2*)&C[(size_t)r0 * 128 + col] =
                    make_float2(acc[mt][nt][0] + bb.x, acc[mt][nt][1] + bb.y);
                if (r1 < M) *(float2*)&C[(size_t)r1 * 128 + col] =
                    make_float2(acc[mt][nt][2] + bb.x, acc[mt][nt][3] + bb.y);
            }
        }
        __syncthreads();
    }
}

// ---------------- fused gate GEMM + sigmoid + LN + leaky_relu -----------------
__global__ __launch_bounds__(256, 2)
void gate_ln(const float* __restrict__ o, const float* __restrict__ r,
             const __nv_bfloat16* __restrict__ w1, const __nv_bfloat16* __restrict__ w2,
             const float* __restrict__ bg, const float* __restrict__ lng,
             const float* __restrict__ lnb, float* __restrict__ out, int M)
{
    extern __shared__ char sm[];
    const int tid = threadIdx.x, wid = tid >> 5, lane = tid & 31;
    const int m0 = blockIdx.x * 64;
    const int wm = (wid >> 2) * 32, wn = (wid & 3) * 32;
    const int group = lane >> 2, tig = lane & 3;

    const uint32_t smb = smem_u32(sm);
    const uint32_t a_off = ((wm + (lane & 15)) * APAD + ((lane >> 4) << 3)) * 2;
    const uint32_t b_off = ((wn + ((lane >> 4) << 3) + (lane & 7)) * APAD + (((lane >> 3) & 1) << 3)) * 2;

    float acc[2][4][4];
    CLEAR_ACC(acc);

    fill_A_f32(sm, o, m0, M, tid);
    fill_B(sm, w1, w1 + 16384, tid);
    __syncthreads();
    mma_tile(smb, a_off, b_off, acc);
    __syncthreads();

    fill_A_f32(sm, r, m0, M, tid);
    fill_B(sm, w2, w2 + 16384, tid);
    __syncthreads();
    mma_tile(smb, a_off, b_off, acc);
    __syncthreads();

    float* hbuf = (float*)sm;
#pragma unroll
    for (int mt = 0; mt < 2; ++mt) {
        int lr0 = wm + mt * 16 + group, lr1 = lr0 + 8;
        int gr0 = m0 + lr0, gr1 = m0 + lr1;
#pragma unroll
        for (int nt = 0; nt < 4; ++nt) {
            int col = wn + nt * 8 + tig * 2;
            float2 bb = *(const float2*)&bg[col];
            if (gr0 < M) {
                float2 ov = *(const float2*)&o[(size_t)gr0 * 128 + col];
                float2 rv = *(const float2*)&r[(size_t)gr0 * 128 + col];
                float b0 = 1.f / (1.f + expf(-(acc[mt][nt][0] + bb.x)));
                float b1 = 1.f / (1.f + expf(-(acc[mt][nt][1] + bb.y)));
                hbuf[lr0 * 132 + col]     = ov.x + b0 * (rv.x - ov.x);
                hbuf[lr0 * 132 + col + 1] = ov.y + b1 * (rv.y - ov.y);
            }
            if (gr1 < M) {
                float2 ov = *(const float2*)&o[(size_t)gr1 * 128 + col];
                float2 rv = *(const float2*)&r[(size_t)gr1 * 128 + col];
                float b0 = 1.f / (1.f + expf(-(acc[mt][nt][2] + bb.x)));
                float b1 = 1.f / (1.f + expf(-(acc[mt][nt][3] + bb.y)));
                hbuf[lr1 * 132 + col]     = ov.x + b0 * (rv.x - ov.x);
                hbuf[lr1 * 132 + col + 1] = ov.y + b1 * (rv.y - ov.y);
            }
        }
    }
    __syncthreads();

#pragma unroll
    for (int i = 0; i < 8; ++i) {
        int row = wid * 8 + i;
        int gr = m0 + row;
        if (gr >= M) continue;
        float4 hv = *(float4*)&hbuf[row * 132 + lane * 4];
        float s1 = hv.x + hv.y + hv.z + hv.w;
        float s2 = hv.x * hv.x + hv.y * hv.y + hv.z * hv.z + hv.w * hv.w;
#pragma unroll
        for (int d = 16; d; d >>= 1) {
            s1 += __shfl_xor_sync(0xFFFFFFFFu, s1, d);
            s2 += __shfl_xor_sync(0xFFFFFFFFu, s2, d);
        }
        float mu = s1 * (1.f / 128.f);
        float var = s2 * (1.f / 128.f) - mu * mu;
        float inv = rsqrtf(var + 1e-5f);
        float4 gv = *(const float4*)&lng[lane * 4];
        float4 bv = *(const float4*)&lnb[lane * 4];
        float4 ov;
        ov.x = (hv.x - mu) * inv * gv.x + bv.x;
        ov.y = (hv.y - mu) * inv * gv.y + bv.y;
        ov.z = (hv.z - mu) * inv * gv.z + bv.z;
        ov.w = (hv.w - mu) * inv * gv.w + bv.w;
        ov.x = ov.x >= 0.f ? ov.x : 0.01f * ov.x;
        ov.y = ov.y >= 0.f ? ov.y : 0.01f * ov.y;
        ov.z = ov.z >= 0.f ? ov.z : 0.01f * ov.z;
        ov.w = ov.w >= 0.f ? ov.w : 0.01f * ov.w;
        *(float4*)&out[(size_t)gr * 128 + lane * 4] = ov;
    }
}

// ---------------- combined weight prep (7 slots, 1 launch) --------------------
__global__ void prep_all(const float* __restrict__ Wq, const float* __restrict__ Wk,
                         const float* __restrict__ Wv, const float* __restrict__ Wr,
                         const float* __restrict__ We, const float* __restrict__ Wg,
                         __nv_bfloat16* __restrict__ wt)
{
    int slot = blockIdx.x >> 6;
    int i = (blockIdx.x & 63) * 256 + threadIdx.x;
    int n = i >> 7, kk = i & 127;
    float f;
    if (slot == 0)      f = Wq[kk * 128 + n];
    else if (slot == 1) f = Wk[kk * 128 + n];
    else if (slot == 2) f = Wv[kk * 128 + n];
    else if (slot == 3) f = Wr[kk * 128 + n];
    else if (slot == 4) f = We[kk * 128 + n];
    else if (slot == 5) f = Wg[kk * 128 + n] + Wg[2 * 16384 + kk * 128 + n];
    else                f = Wg[16384 + kk * 128 + n] - Wg[2 * 16384 + kk * 128 + n];
    __nv_bfloat16 h = __float2bfloat16(f);
    wt[slot * 32768 + i] = h;
    wt[slot * 32768 + 16384 + i] = __float2bfloat16(f - __bfloat162float(h));
}

__global__ void prep_x(const float* __restrict__ X, __nv_bfloat16* __restrict__ xh,
                       __nv_bfloat16* __restrict__ xl, int n4)
{
    int i = blockIdx.x * 256 + threadIdx.x;
    if (i < n4) {
        float4 v = *(const float4*)&X[(size_t)i * 4];
        uint32_t hp0 = cvt2(v.x, v.y);
        uint32_t hp1 = cvt2(v.z, v.w);
        float lx = v.x - __uint_as_float(hp0 << 16);
        float ly = v.y - __uint_as_float(hp0 & 0xFFFF0000u);
        float lz = v.z - __uint_as_float(hp1 << 16);
        float lw = v.w - __uint_as_float(hp1 & 0xFFFF0000u);
        *(uint2*)&xh[(size_t)i * 4] = make_uint2(hp0, hp1);
        *(uint2*)&xl[(size_t)i * 4] = make_uint2(cvt2(lx, ly), cvt2(lz, lw));
    }
}

// ---------------- CSR build: hist + 3-phase grid scan + scatter ----------------
__global__ void hist_kernel(const int* __restrict__ dst, int* __restrict__ counts, int E)
{
    int i = blockIdx.x * blockDim.x + threadIdx.x;
    if (i < E) atomicAdd(&counts[dst[i]], 1);
}

__global__ void scan_part(const int* __restrict__ counts, int* __restrict__ bsum, int N)
{
    __shared__ int wtot[8];
    int t = threadIdx.x, wid = t >> 5, lane = t & 31;
    int s = 0;
#pragma unroll
    for (int i = 0; i < 8; ++i) {
        int idx = blockIdx.x * 2048 + t * 8 + i;
        if (idx < N) s += counts[idx];
    }
#pragma unroll
    for (int d = 16; d; d >>= 1) s += __shfl_xor_sync(0xFFFFFFFFu, s, d);
    if (lane == 0) wtot[wid] = s;
    __syncthreads();
    if (t == 0) {
        int tot = 0;
#pragma unroll
        for (int i = 0; i < 8; ++i) tot += wtot[i];
        bsum[blockIdx.x] = tot;
    }
}
__global__ void scan_mid(int* __restrict__ bsum, int nb, int* __restrict__ off, int N, int E)
{
    int lane = threadIdx.x;
    int v = (lane < nb) ? bsum[lane] : 0;
    int orig = v;
#pragma unroll
    for (int d = 1; d < 32; d <<= 1) {
        int u = __shfl_up_sync(0xFFFFFFFFu, v, d);
        if (lane >= d) v += u;
    }
    if (lane < nb) bsum[lane] = v - orig;
    if (lane == 0) off[N] = E;
}
__global__ void scan_final(const int* __restrict__ counts, const int* __restrict__ bsum,
                           int* __restrict__ off, int* __restrict__ cursor, int N)
{
    __shared__ int wtot[8];
    int t = threadIdx.x, wid = t >> 5, lane = t & 31;
    int base = blockIdx.x * 2048 + t * 8;
    int c[8];
    int s = 0;
#pragma unroll
    for (int i = 0; i < 8; ++i) {
        int idx = base + i;
        c[i] = (idx < N) ? counts[idx] : 0;
        s += c[i];
    }
    int incl = s;
#pragma unroll
    for (int d = 1; d < 32; d <<= 1) {
        int u = __shfl_up_sync(0xFFFFFFFFu, incl, d);
        if (lane >= d) incl += u;
    }
    if (lane == 31) wtot[wid] = incl;
    __syncthreads();
    int wbase = 0;
#pragma unroll
    for (int i = 0; i < 8; ++i) wbase += (i < wid) ? wtot[i] : 0;
    int run = bsum[blockIdx.x] + wbase + (incl - s);
#pragma unroll
    for (int i = 0; i < 8; ++i) {
        int idx = base + i;
        if (idx < N) { off[idx] = run; cursor[idx] = run; }
        run += c[i];
    }
}

__global__ void scatter_kernel(const int* __restrict__ dst, int* __restrict__ cursor,
                               int* __restrict__ elist, int E)
{
    int i = blockIdx.x * blockDim.x + threadIdx.x;
    if (i < E) {
        int p = atomicAdd(&cursor[dst[i]], 1);
        elist[p] = i;
    }
}

// ---------------- fused per-node sweep: score + softmax + aggregate + out2 -----
// chunked (4 edges) manual pipeline: indices, then rows, then math
__global__ void aggregate(const float* __restrict__ e, const float* __restrict__ v,
                          const float* __restrict__ q, const float* __restrict__ k,
                          const int* __restrict__ src,
                          const int* __restrict__ off, const int* __restrict__ elist,
                          float* __restrict__ escore,
                          float* __restrict__ o, float* __restrict__ out2, int N)
{
    int w = (blockIdx.x * blockDim.x + threadIdx.x) >> 5;
    int lane = threadIdx.x & 31;
    if (w >= N) return;
    int hl = lane >> 2;
    int beg = off[w], end = off[w + 1];
    float4 qv = *(const float4*)&q[(size_t)w * 128 + (lane << 2)];
    float zl = 0.f;
    float ax = 0.f, ay = 0.f, az = 0.f, aw = 0.f;

    for (int base = beg; base < end; base += 4) {
        int n = end - base; if (n > 4) n = 4;
        int eids[4], ss[4];
#pragma unroll
        for (int j = 0; j < 4; ++j)
            eids[j] = (j < n) ? elist[base + j] : eids[0];
#pragma unroll
        for (int j = 0; j < 4; ++j)
            ss[j] = (j < n) ? src[eids[j]] : ss[0];
        float4 evs[4], kvs[4], vvs[4];
#pragma unroll
        for (int j = 0; j < 4; ++j) {
            if (j < n) {
                evs[j] = *(const float4*)&e[(size_t)eids[j] * 128 + (lane << 2)];
                kvs[j] = *(const float4*)&k[(size_t)ss[j] * 128 + (lane << 2)];
                vvs[j] = *(const float4*)&v[(size_t)ss[j] * 128 + (lane << 2)];
            }
        }
#pragma unroll
        for (int j = 0; j < 4; ++j) {
            if (j >= n) break;
            float4 ev = evs[j], kv = kvs[j], vv = vvs[j];
            float p = qv.x * (kv.x + ev.x) + qv.y * (kv.y + ev.y)
                    + qv.z * (kv.z + ev.z) + qv.w * (kv.w + ev.w);
            p += __shfl_xor_sync(0xFFFFFFFFu, p, 1);
            p += __shfl_xor_sync(0xFFFFFFFFu, p, 2);
            float esc = expf(p);
            zl += esc;
            ax += esc * (ev.x + vv.x);
            ay += esc * (ev.y + vv.y);
            az += esc * (ev.z + vv.z);
            aw += esc * (ev.w + vv.w);
            if ((lane & 3) == 0) escore[(size_t)eids[j] * 8 + hl] = esc;
        }
    }

    float sc = 0.25f / (1e-8f + zl);
    float4 ov; ov.x = ax * sc; ov.y = ay * sc; ov.z = az * sc; ov.w = aw * sc;
    *(float4*)&o[(size_t)w * 128 + (lane << 2)] = ov;

    // out2 pass: 4 edges x 8 heads per step, all 32 lanes active
    int myh = lane & 7;
    float myhsc = __shfl_sync(0xFFFFFFFFu, sc, myh * 4);
    for (int idx = beg + (lane >> 3); idx < end; idx += 4) {
        int eid = elist[idx];
        out2[(size_t)eid * 8 + myh] = myhsc * escore[(size_t)eid * 8 + myh];
    }
}

// ---------------- launch ---------------------------------------------------------
extern "C" void kernel_launch(void* const* d_in, const int* in_sizes, int n_in,
                              void* d_out, int out_size)
{
    const float* x   = (const float*)d_in[0];
    const float* y   = (const float*)d_in[1];
    const int*   src = (const int*)d_in[2];
    const int*   dst = (const int*)d_in[3];
    const float* Wq  = (const float*)d_in[4];
    const float* bq  = (const float*)d_in[5];
    const float* Wk  = (const float*)d_in[6];
    const float* bk  = (const float*)d_in[7];
    const float* Wv  = (const float*)d_in[8];
    const float* bv  = (const float*)d_in[9];
    const float* We  = (const float*)d_in[10];
    const float* be  = (const float*)d_in[11];
    const float* Wr  = (const float*)d_in[12];
    const float* br  = (const float*)d_in[13];
    const float* Wg  = (const float*)d_in[14];
    const float* bg  = (const float*)d_in[15];
    const float* lng = (const float*)d_in[16];
    const float* lnb = (const float*)d_in[17];

    const int N = in_sizes[0] / 128;
    const int E = in_sizes[2];

    float *q, *k, *v, *r, *o, *e, *escore;
    __nv_bfloat16 *wt, *xh, *xl;
    int *counts, *off, *cursor, *elist, *bsum;
    void* p;
    cudaGetSymbolAddress(&p, g_q);      q = (float*)p;
    cudaGetSymbolAddress(&p, g_k);      k = (float*)p;
    cudaGetSymbolAddress(&p, g_v);      v = (float*)p;
    cudaGetSymbolAddress(&p, g_r);      r = (float*)p;
    cudaGetSymbolAddress(&p, g_o);      o = (float*)p;
    cudaGetSymbolAddress(&p, g_e);      e = (float*)p;
    cudaGetSymbolAddress(&p, g_escore); escore = (float*)p;
    cudaGetSymbolAddress(&p, g_wt);     wt = (__nv_bfloat16*)p;
    cudaGetSymbolAddress(&p, g_xh);     xh = (__nv_bfloat16*)p;
    cudaGetSymbolAddress(&p, g_xl);     xl = (__nv_bfloat16*)p;
    cudaGetSymbolAddress(&p, g_counts); counts = (int*)p;
    cudaGetSymbolAddress(&p, g_off);    off = (int*)p;
    cudaGetSymbolAddress(&p, g_cursor); cursor = (int*)p;
    cudaGetSymbolAddress(&p, g_elist);  elist = (int*)p;
    cudaGetSymbolAddress(&p, g_bsum);   bsum = (int*)p;

    cudaFuncSetAttribute(tc_gemm,   cudaFuncAttributeMaxDynamicSharedMemorySize, SMEM_EP);
    cudaFuncSetAttribute(qkvr_gemm, cudaFuncAttributeMaxDynamicSharedMemorySize, SMEM_G);
    cudaFuncSetAttribute(gate_ln,   cudaFuncAttributeMaxDynamicSharedMemorySize, SMEM_G);

    float* out  = (float*)d_out;
    float* out2 = out + (size_t)N * 128;

    __nv_bfloat16* we_h = wt + 4 * 32768; __nv_bfloat16* we_l = we_h + 16384;
    __nv_bfloat16* w1_h = wt + 5 * 32768;
    __nv_bfloat16* w2_h = wt + 6 * 32768;

    const int gN = (N + 63) / 64;
    const int nb = (N + 2047) / 2048;
    const int numTiles = (E + 127) / 128;
    const int gPersist = numTiles < 148 ? numTiles : 148;

    static cudaStream_t s1 = nullptr, s2 = nullptr;
    static cudaEvent_t evFork = nullptr, evJ1 = nullptr, evJ2 = nullptr;
    if (s1 == nullptr) {
        cudaStreamCreateWithFlags(&s1, cudaStreamNonBlocking);
        cudaStreamCreateWithFlags(&s2, cudaStreamNonBlocking);
        cudaEventCreateWithFlags(&evFork, cudaEventDisableTiming);
        cudaEventCreateWithFlags(&evJ1,   cudaEventDisableTiming);
        cudaEventCreateWithFlags(&evJ2,   cudaEventDisableTiming);
    }

    prep_all<<<448, 256>>>(Wq, Wk, Wv, Wr, We, Wg, wt);
    cudaEventRecord(evFork, 0);
    cudaStreamWaitEvent(s1, evFork, 0);
    cudaStreamWaitEvent(s2, evFork, 0);

    tc_gemm<<<gPersist, 256, SMEM_EP, 0>>>(y, we_h, we_l, be, e, E);

    prep_x<<<(N * 32 + 255) / 256, 256, 0, s1>>>(x, xh, xl, N * 32);
    qkvr_gemm<<<gN, 256, SMEM_G, s1>>>(xh, xl, wt, bq, bk, bv, br, q, k, v, r, N);

    cudaMemsetAsync(counts, 0, (size_t)N * sizeof(int), s2);
    hist_kernel<<<(E + 255) / 256, 256, 0, s2>>>(dst, counts, E);
    scan_part<<<nb, 256, 0, s2>>>(counts, bsum, N);
    scan_mid<<<1, 32, 0, s2>>>(bsum, nb, off, N, E);
    scan_final<<<nb, 256, 0, s2>>>(counts, bsum, off, cursor, N);
    scatter_kernel<<<(E + 255) / 256, 256, 0, s2>>>(dst, cursor, elist, E);

    cudaEventRecord(evJ1, s1);
    cudaEventRecord(evJ2, s2);
    cudaStreamWaitEvent(0, evJ1, 0);
    cudaStreamWaitEvent(0, evJ2, 0);

    aggregate<<<(N + 7) / 8, 256>>>(e, v, q, k, src, off, elist, escore, o, out2, N);
    gate_ln<<<gN, 256, SMEM_G>>>(o, r, w1_h, w2_h, bg, lng, lnb, out, N);
}

// round 15
// speedup vs baseline: 1.1841x; 1.1841x over previous
#include <cuda_runtime.h>
#include <cuda_bf16.h>
#include <cstdint>
#include <math.h>

#define NMAX 50016
#define EMAX 800032

// ---------------- scratch (device globals; no runtime allocation) ------------
__device__ float g_q[NMAX * 128];
__device__ float g_k[NMAX * 128];
__device__ float g_v[NMAX * 128];
__device__ float g_r[NMAX * 128];
__device__ float g_o[NMAX * 128];
__device__ float g_e[(size_t)EMAX * 128];
__device__ float g_escore[EMAX * 8];
__device__ __nv_bfloat16 g_wt[7 * 2 * 16384];   // [slot][hi/lo][n*128+k]
__device__ __nv_bfloat16 g_xh[NMAX * 128];
__device__ __nv_bfloat16 g_xl[NMAX * 128];
__device__ int   g_counts[NMAX + 8];
__device__ int   g_off[NMAX + 8];
__device__ int   g_cursor[NMAX + 8];
__device__ int   g_elist[EMAX];
__device__ int   g_bsum[64];

__device__ __forceinline__ uint32_t smem_u32(const void* p) {
    uint32_t a;
    asm("{ .reg .u64 t; cvta.to.shared.u64 t, %1; cvt.u32.u64 %0, t; }" : "=r"(a) : "l"(p));
    return a;
}
__device__ __forceinline__ void ldsm4(uint32_t* r, uint32_t addr) {
    asm volatile("ldmatrix.sync.aligned.m8n8.x4.shared.b16 {%0,%1,%2,%3}, [%4];"
        : "=r"(r[0]), "=r"(r[1]), "=r"(r[2]), "=r"(r[3]) : "r"(addr));
}
__device__ __forceinline__ uint32_t cvt2(float x, float y) {
    uint32_t d;
    asm("cvt.rn.bf16x2.f32 %0, %1, %2;" : "=r"(d) : "f"(y), "f"(x));
    return d;
}
__device__ __forceinline__ void mma16816(float* c, const uint32_t* a, uint32_t b0, uint32_t b1) {
    asm volatile("mma.sync.aligned.m16n8k16.row.col.f32.bf16.bf16.f32 "
        "{%0,%1,%2,%3}, {%4,%5,%6,%7}, {%8,%9}, {%0,%1,%2,%3};"
        : "+f"(c[0]), "+f"(c[1]), "+f"(c[2]), "+f"(c[3])
        : "r"(a[0]), "r"(a[1]), "r"(a[2]), "r"(a[3]), "r"(b0), "r"(b1));
}
__device__ __forceinline__ void cp_async16(uint32_t dst, const void* src) {
    asm volatile("cp.async.cg.shared.global [%0], [%1], 16;" :: "r"(dst), "l"(src));
}
#define CP_COMMIT() asm volatile("cp.async.commit_group;" ::: "memory")
#define CP_WAIT0()  asm volatile("cp.async.wait_group 0;" ::: "memory")

// ---------------- shared tile constants ---------------------------------------
#define APAD 136
#define MT_STRIDE (16 * APAD * 2)

// === framework A: BM=64, 256 thr, warp 32x32 (qkvr_gemm / gate_ln) ============
#define A_BYTES (64 * APAD * 2)
#define B_BYTES (128 * APAD * 2)
#define SMEM_G (2 * A_BYTES + 2 * B_BYTES)      // 104448
#define OFF_AH 0
#define OFF_AL A_BYTES
#define OFF_BH (2 * A_BYTES)
#define OFF_BL (2 * A_BYTES + B_BYTES)

__device__ __forceinline__ void fill_A_f32(char* sm, const float* Ag, int m0, int M, int tid) {
#pragma unroll
    for (int i = 0; i < 8; ++i) {
        int t4 = tid + i * 256;
        int m = t4 >> 5, c4 = t4 & 31;
        float4 v = make_float4(0.f, 0.f, 0.f, 0.f);
        if (m0 + m < M) v = *(const float4*)&Ag[(size_t)(m0 + m) * 128 + (c4 << 2)];
        uint32_t hp0 = cvt2(v.x, v.y), hp1 = cvt2(v.z, v.w);
        float lx = v.x - __uint_as_float(hp0 << 16);
        float ly = v.y - __uint_as_float(hp0 & 0xFFFF0000u);
        float lz = v.z - __uint_as_float(hp1 << 16);
        float lw = v.w - __uint_as_float(hp1 & 0xFFFF0000u);
        int boff = (m * APAD + (c4 << 2)) * 2;
        *(uint2*)(sm + OFF_AH + boff) = make_uint2(hp0, hp1);
        *(uint2*)(sm + OFF_AL + boff) = make_uint2(cvt2(lx, ly), cvt2(lz, lw));
    }
}
__device__ __forceinline__ void fill_A_bf16(char* sm, const __nv_bfloat16* Agh,
                                            const __nv_bfloat16* Agl, int m0, int M, int tid) {
#pragma unroll
    for (int i = 0; i < 4; ++i) {
        int t = tid + i * 256;
        int m = t >> 4, c8 = (t & 15) << 3;
        uint4 vh = make_uint4(0, 0, 0, 0), vl = make_uint4(0, 0, 0, 0);
        if (m0 + m < M) {
            vh = *(const uint4*)&Agh[(size_t)(m0 + m) * 128 + c8];
            vl = *(const uint4*)&Agl[(size_t)(m0 + m) * 128 + c8];
        }
        int boff = (m * APAD + c8) * 2;
        *(uint4*)(sm + OFF_AH + boff) = vh;
        *(uint4*)(sm + OFF_AL + boff) = vl;
    }
}
__device__ __forceinline__ void fill_B(char* sm, const __nv_bfloat16* Wth,
                                       const __nv_bfloat16* Wtl, int tid) {
#pragma unroll
    for (int i = 0; i < 8; ++i) {
        int t = tid + i * 256;
        int n = t >> 4, k8 = (t & 15) << 3;
        int boff = (n * APAD + k8) * 2;
        *(uint4*)(sm + OFF_BH + boff) = *(const uint4*)&Wth[n * 128 + k8];
        *(uint4*)(sm + OFF_BL + boff) = *(const uint4*)&Wtl[n * 128 + k8];
    }
}
__device__ __forceinline__ void mma_tile(uint32_t smb, uint32_t a_off, uint32_t b_off,
                                         float acc[2][4][4]) {
    const uint32_t AHs = smb + OFF_AH, ALs = smb + OFF_AL;
    const uint32_t BHs = smb + OFF_BH, BLs = smb + OFF_BL;
#pragma unroll
    for (int ks = 0; ks < 8; ++ks) {
        const uint32_t kb = ks * 32;
        uint32_t ah[2][4], al[2][4], bh[2][4], bl[2][4];
#pragma unroll
        for (int mt = 0; mt < 2; ++mt) {
            ldsm4(ah[mt], AHs + a_off + mt * MT_STRIDE + kb);
            ldsm4(al[mt], ALs + a_off + mt * MT_STRIDE + kb);
        }
#pragma unroll
        for (int p = 0; p < 2; ++p) {
            ldsm4(bh[p], BHs + b_off + p * MT_STRIDE + kb);
            ldsm4(bl[p], BLs + b_off + p * MT_STRIDE + kb);
        }
#pragma unroll
        for (int mt = 0; mt < 2; ++mt)
#pragma unroll
            for (int nt = 0; nt < 4; ++nt) {
                uint32_t b0h = bh[nt >> 1][(nt & 1) * 2], b1h = bh[nt >> 1][(nt & 1) * 2 + 1];
                uint32_t b0l = bl[nt >> 1][(nt & 1) * 2], b1l = bl[nt >> 1][(nt & 1) * 2 + 1];
                mma16816(acc[mt][nt], ah[mt], b0h, b1h);
                mma16816(acc[mt][nt], al[mt], b0h, b1h);
                mma16816(acc[mt][nt], ah[mt], b0l, b1l);
            }
    }
}
#define CLEAR_ACC(acc) \
    _Pragma("unroll") for (int _a = 0; _a < 2; ++_a) \
    _Pragma("unroll") for (int _b = 0; _b < 4; ++_b) \
    _Pragma("unroll") for (int _c = 0; _c < 4; ++_c) acc[_a][_b][_c] = 0.f;

// === framework B: persistent BM=128, double-buffered A, pipelined convert =====
#define A2_BYTES (128 * APAD * 2)               // 34816
#define E_BH (4 * A2_BYTES)
#define E_BL (5 * A2_BYTES)
#define SMEM_EP (6 * A2_BYTES)                  // 208896

__device__ __forceinline__ void conv_store(char* sm, uint32_t ah_base_off, uint32_t al_base_off,
                                           int chunk, int tid, const float4& v0, const float4& v1) {
    int c = tid + chunk * 256;
    int m = c >> 4, col8 = (c & 15) << 3;
    uint32_t h0 = cvt2(v0.x, v0.y), h1 = cvt2(v0.z, v0.w);
    uint32_t h2 = cvt2(v1.x, v1.y), h3 = cvt2(v1.z, v1.w);
    float l0x = v0.x - __uint_as_float(h0 << 16);
    float l0y = v0.y - __uint_as_float(h0 & 0xFFFF0000u);
    float l0z = v0.z - __uint_as_float(h1 << 16);
    float l0w = v0.w - __uint_as_float(h1 & 0xFFFF0000u);
    float l1x = v1.x - __uint_as_float(h2 << 16);
    float l1y = v1.y - __uint_as_float(h2 & 0xFFFF0000u);
    float l1z = v1.z - __uint_as_float(h3 << 16);
    float l1w = v1.w - __uint_as_float(h3 & 0xFFFF0000u);
    int boff = (m * APAD + col8) * 2;
    *(uint4*)(sm + ah_base_off + boff) = make_uint4(h0, h1, h2, h3);
    *(uint4*)(sm + al_base_off + boff) = make_uint4(cvt2(l0x, l0y), cvt2(l0z, l0w),
                                                    cvt2(l1x, l1y), cvt2(l1z, l1w));
}

__global__ __launch_bounds__(256, 1)
void tc_gemm(const float* __restrict__ A,
             const __nv_bfloat16* __restrict__ Wt_h, const __nv_bfloat16* __restrict__ Wt_l,
             const float* __restrict__ bias, float* __restrict__ C, int M)
{
    extern __shared__ char sm[];
    const int tid = threadIdx.x, wid = tid >> 5, lane = tid & 31;
    const int wm = (wid >> 2) * 64, wn = (wid & 3) * 32;
    const int group = lane >> 2, tig = lane & 3;
    const uint32_t smb = smem_u32(sm);
    const int numTiles = (M + 127) >> 7;

#pragma unroll
    for (int i = 0; i < 8; ++i) {
        int t = tid + i * 256;
        int n = t >> 4, k8 = (t & 15) << 3;
        uint32_t boff = (uint32_t)(n * APAD + k8) * 2;
        cp_async16(smb + E_BH + boff, &Wt_h[n * 128 + k8]);
        cp_async16(smb + E_BL + boff, &Wt_l[n * 128 + k8]);
    }
    CP_COMMIT();

    if ((int)blockIdx.x < numTiles) {
        int m0 = blockIdx.x * 128;
#pragma unroll
        for (int i = 0; i < 8; ++i) {
            int c = tid + i * 256;
            int m = c >> 4, col8 = (c & 15) << 3;
            float4 v0 = make_float4(0.f, 0.f, 0.f, 0.f), v1 = v0;
            if (m0 + m < M) {
                v0 = *(const float4*)&A[(size_t)(m0 + m) * 128 + col8];
                v1 = *(const float4*)&A[(size_t)(m0 + m) * 128 + col8 + 4];
            }
            conv_store(sm, 0, A2_BYTES, i, tid, v0, v1);
        }
    }
    CP_WAIT0();
    __syncthreads();

    const uint32_t BHs = smb + E_BH, BLs = smb + E_BL;
    const uint32_t a_off = ((wm + (lane & 15)) * APAD + ((lane >> 4) << 3)) * 2;
    const uint32_t b_off = ((wn + ((lane >> 4) << 3) + (lane & 7)) * APAD + (((lane >> 3) & 1) << 3)) * 2;

    int buf = 0;
    for (int t = blockIdx.x; t < numTiles; t += gridDim.x) {
        const int m0 = t * 128;
        const int tn = t + gridDim.x;
        const bool hasNext = (tn < numTiles);
        const int m0n = tn * 128;
        const uint32_t AHs = smb + (uint32_t)buf * 2 * A2_BYTES;
        const uint32_t ALs = AHs + A2_BYTES;
        const uint32_t ah_n = (uint32_t)(buf ^ 1) * 2 * A2_BYTES;
        const uint32_t al_n = ah_n + A2_BYTES;

        float acc[4][4][4];
#pragma unroll
        for (int a = 0; a < 4; ++a)
#pragma unroll
            for (int b = 0; b < 4; ++b)
#pragma unroll
                for (int c = 0; c < 4; ++c) acc[a][b][c] = 0.f;

        float4 pv[2][2];

#pragma unroll
        for (int ks = 0; ks < 8; ++ks) {
            if (hasNext && ks >= 2)
                conv_store(sm, ah_n, al_n, ks - 2, tid, pv[ks & 1][0], pv[ks & 1][1]);
            if (hasNext) {
                int c = tid + ks * 256;
                int m = c >> 4, col8 = (c & 15) << 3;
                if (m0n + m < M) {
                    pv[ks & 1][0] = *(const float4*)&A[(size_t)(m0n + m) * 128 + col8];
                    pv[ks & 1][1] = *(const float4*)&A[(size_t)(m0n + m) * 128 + col8 + 4];
                } else {
                    pv[ks & 1][0] = make_float4(0.f, 0.f, 0.f, 0.f);
                    pv[ks & 1][1] = make_float4(0.f, 0.f, 0.f, 0.f);
                }
            }
            const uint32_t kb = ks * 32;
            uint32_t ah[4][4], al[4][4], bh[2][4], bl[2][4];
#pragma unroll
            for (int mt = 0; mt < 4; ++mt) {
                ldsm4(ah[mt], AHs + a_off + mt * MT_STRIDE + kb);
                ldsm4(al[mt], ALs + a_off + mt * MT_STRIDE + kb);
            }
#pragma unroll
            for (int p = 0; p < 2; ++p) {
                ldsm4(bh[p], BHs + b_off + p * MT_STRIDE + kb);
                ldsm4(bl[p], BLs + b_off + p * MT_STRIDE + kb);
            }
#pragma unroll
            for (int mt = 0; mt < 4; ++mt)
#pragma unroll
                for (int nt = 0; nt < 4; ++nt) {
                    uint32_t b0h = bh[nt >> 1][(nt & 1) * 2], b1h = bh[nt >> 1][(nt & 1) * 2 + 1];
                    uint32_t b0l = bl[nt >> 1][(nt & 1) * 2], b1l = bl[nt >> 1][(nt & 1) * 2 + 1];
                    mma16816(acc[mt][nt], ah[mt], b0h, b1h);
                    mma16816(acc[mt][nt], al[mt], b0h, b1h);
                    mma16816(acc[mt][nt], ah[mt], b0l, b1l);
                }
        }
        if (hasNext) {
            conv_store(sm, ah_n, al_n, 6, tid, pv[0][0], pv[0][1]);
            conv_store(sm, ah_n, al_n, 7, tid, pv[1][0], pv[1][1]);
        }

#pragma unroll
        for (int mt = 0; mt < 4; ++mt) {
            int r0 = m0 + wm + mt * 16 + group, r1 = r0 + 8;
#pragma unroll
            for (int nt = 0; nt < 4; ++nt) {
                int col = wn + nt * 8 + tig * 2;
                float2 bb = *(const float2*)&bias[col];
                if (r0 < M) *(float2*)&C[(size_t)r0 * 128 + col] =
                    make_float2(acc[mt][nt][0] + bb.x, acc[mt][nt][1] + bb.y);
                if (r1 < M) *(float2*)&C[(size_t)r1 * 128 + col] =
                    make_float2(acc[mt][nt][2] + bb.x, acc[mt][nt][3] + bb.y);
            }
        }
        __syncthreads();
        buf ^= 1;
    }
}

// ---------------- fused QKVR: 4 GEMMs sharing one A tile ----------------------
__global__ __launch_bounds__(256, 2)
void qkvr_gemm(const __nv_bfloat16* __restrict__ xh, const __nv_bfloat16* __restrict__ xl,
               const __nv_bfloat16* __restrict__ wt,
               const float* __restrict__ bq, const float* __restrict__ bk,
               const float* __restrict__ bv, const float* __restrict__ br,
               float* __restrict__ q, float* __restrict__ k,
               float* __restrict__ v, float* __restrict__ r, int M)
{
    extern __shared__ char sm[];
    const int tid = threadIdx.x, wid = tid >> 5, lane = tid & 31;
    const int m0 = blockIdx.x * 64;
    const int wm = (wid >> 2) * 32, wn = (wid & 3) * 32;
    const int group = lane >> 2, tig = lane & 3;

    fill_A_bf16(sm, xh, xl, m0, M, tid);

    const uint32_t smb = smem_u32(sm);
    const uint32_t a_off = ((wm + (lane & 15)) * APAD + ((lane >> 4) << 3)) * 2;
    const uint32_t b_off = ((wn + ((lane >> 4) << 3) + (lane & 7)) * APAD + (((lane >> 3) & 1) << 3)) * 2;

    const float* bs[4] = {bq, bk, bv, br};
    float* outs[4] = {q, k, v, r};

#pragma unroll
    for (int w = 0; w < 4; ++w) {
        fill_B(sm, wt + w * 32768, wt + w * 32768 + 16384, tid);
        __syncthreads();

        float acc[2][4][4];
        CLEAR_ACC(acc);
        mma_tile(smb, a_off, b_off, acc);

        const float* bias = bs[w];
        float* C = outs[w];
#pragma unroll
        for (int mt = 0; mt < 2; ++mt) {
            int r0 = m0 + wm + mt * 16 + group, r1 = r0 + 8;
#pragma unroll
            for (int nt = 0; nt < 4; ++nt) {
                int col = wn + nt * 8 + tig * 2;
                float2 bb = *(const float2*)&bias[col];
                if (r0 < M) *(float2*)&C[(size_t)r0 * 128 + col] =
                    make_float2(acc[mt][nt][0] + bb.x, acc[mt][nt][1] + bb.y);
                if (r1 < M) *(float2*)&C[(size_t)r1 * 128 + col] =
                    make_float2(acc[mt][nt][2] + bb.x, acc[mt][nt][3] + bb.y);
            }
        }
        __syncthreads();
    }
}

// ---------------- fused gate GEMM + sigmoid + LN + leaky_relu -----------------
__global__ __launch_bounds__(256, 2)
void gate_ln(const float* __restrict__ o, const float* __restrict__ r,
             const __nv_bfloat16* __restrict__ w1, const __nv_bfloat16* __restrict__ w2,
             const float* __restrict__ bg, const float* __restrict__ lng,
             const float* __restrict__ lnb, float* __restrict__ out, int M)
{
    extern __shared__ char sm[];
    const int tid = threadIdx.x, wid = tid >> 5, lane = tid & 31;
    const int m0 = blockIdx.x * 64;
    const int wm = (wid >> 2) * 32, wn = (wid & 3) * 32;
    const int group = lane >> 2, tig = lane & 3;

    const uint32_t smb = smem_u32(sm);
    const uint32_t a_off = ((wm + (lane & 15)) * APAD + ((lane >> 4) << 3)) * 2;
    const uint32_t b_off = ((wn + ((lane >> 4) << 3) + (lane & 7)) * APAD + (((lane >> 3) & 1) << 3)) * 2;

    float acc[2][4][4];
    CLEAR_ACC(acc);

    fill_A_f32(sm, o, m0, M, tid);
    fill_B(sm, w1, w1 + 16384, tid);
    __syncthreads();
    mma_tile(smb, a_off, b_off, acc);
    __syncthreads();

    fill_A_f32(sm, r, m0, M, tid);
    fill_B(sm, w2, w2 + 16384, tid);
    __syncthreads();
    mma_tile(smb, a_off, b_off, acc);
    __syncthreads();

    float* hbuf = (float*)sm;
#pragma unroll
    for (int mt = 0; mt < 2; ++mt) {
        int lr0 = wm + mt * 16 + group, lr1 = lr0 + 8;
        int gr0 = m0 + lr0, gr1 = m0 + lr1;
#pragma unroll
        for (int nt = 0; nt < 4; ++nt) {
            int col = wn + nt * 8 + tig * 2;
            float2 bb = *(const float2*)&bg[col];
            if (gr0 < M) {
                float2 ov = *(const float2*)&o[(size_t)gr0 * 128 + col];
                float2 rv = *(const float2*)&r[(size_t)gr0 * 128 + col];
                float b0 = 1.f / (1.f + expf(-(acc[mt][nt][0] + bb.x)));
                float b1 = 1.f / (1.f + expf(-(acc[mt][nt][1] + bb.y)));
                hbuf[lr0 * 132 + col]     = ov.x + b0 * (rv.x - ov.x);
                hbuf[lr0 * 132 + col + 1] = ov.y + b1 * (rv.y - ov.y);
            }
            if (gr1 < M) {
                float2 ov = *(const float2*)&o[(size_t)gr1 * 128 + col];
                float2 rv = *(const float2*)&r[(size_t)gr1 * 128 + col];
                float b0 = 1.f / (1.f + expf(-(acc[mt][nt][2] + bb.x)));
                float b1 = 1.f / (1.f + expf(-(acc[mt][nt][3] + bb.y)));
                hbuf[lr1 * 132 + col]     = ov.x + b0 * (rv.x - ov.x);
                hbuf[lr1 * 132 + col + 1] = ov.y + b1 * (rv.y - ov.y);
            }
        }
    }
    __syncthreads();

#pragma unroll
    for (int i = 0; i < 8; ++i) {
        int row = wid * 8 + i;
        int gr = m0 + row;
        if (gr >= M) continue;
        float4 hv = *(float4*)&hbuf[row * 132 + lane * 4];
        float s1 = hv.x + hv.y + hv.z + hv.w;
        float s2 = hv.x * hv.x + hv.y * hv.y + hv.z * hv.z + hv.w * hv.w;
#pragma unroll
        for (int d = 16; d; d >>= 1) {
            s1 += __shfl_xor_sync(0xFFFFFFFFu, s1, d);
            s2 += __shfl_xor_sync(0xFFFFFFFFu, s2, d);
        }
        float mu = s1 * (1.f / 128.f);
        float var = s2 * (1.f / 128.f) - mu * mu;
        float inv = rsqrtf(var + 1e-5f);
        float4 gv = *(const float4*)&lng[lane * 4];
        float4 bv = *(const float4*)&lnb[lane * 4];
        float4 ov;
        ov.x = (hv.x - mu) * inv * gv.x + bv.x;
        ov.y = (hv.y - mu) * inv * gv.y + bv.y;
        ov.z = (hv.z - mu) * inv * gv.z + bv.z;
        ov.w = (hv.w - mu) * inv * gv.w + bv.w;
        ov.x = ov.x >= 0.f ? ov.x : 0.01f * ov.x;
        ov.y = ov.y >= 0.f ? ov.y : 0.01f * ov.y;
        ov.z = ov.z >= 0.f ? ov.z : 0.01f * ov.z;
        ov.w = ov.w >= 0.f ? ov.w : 0.01f * ov.w;
        *(float4*)&out[(size_t)gr * 128 + lane * 4] = ov;
    }
}

// ---------------- combined weight prep (7 slots, 1 launch) --------------------
__global__ void prep_all(const float* __restrict__ Wq, const float* __restrict__ Wk,
                         const float* __restrict__ Wv, const float* __restrict__ Wr,
                         const float* __restrict__ We, const float* __restrict__ Wg,
                         __nv_bfloat16* __restrict__ wt)
{
    int slot = blockIdx.x >> 6;
    int i = (blockIdx.x & 63) * 256 + threadIdx.x;
    int n = i >> 7, kk = i & 127;
    float f;
    if (slot == 0)      f = Wq[kk * 128 + n];
    else if (slot == 1) f = Wk[kk * 128 + n];
    else if (slot == 2) f = Wv[kk * 128 + n];
    else if (slot == 3) f = Wr[kk * 128 + n];
    else if (slot == 4) f = We[kk * 128 + n];
    else if (slot == 5) f = Wg[kk * 128 + n] + Wg[2 * 16384 + kk * 128 + n];
    else                f = Wg[16384 + kk * 128 + n] - Wg[2 * 16384 + kk * 128 + n];
    __nv_bfloat16 h = __float2bfloat16(f);
    wt[slot * 32768 + i] = h;
    wt[slot * 32768 + 16384 + i] = __float2bfloat16(f - __bfloat162float(h));
}

__global__ void prep_x(const float* __restrict__ X, __nv_bfloat16* __restrict__ xh,
                       __nv_bfloat16* __restrict__ xl, int n4)
{
    int i = blockIdx.x * 256 + threadIdx.x;
    if (i < n4) {
        float4 v = *(const float4*)&X[(size_t)i * 4];
        uint32_t hp0 = cvt2(v.x, v.y);
        uint32_t hp1 = cvt2(v.z, v.w);
        float lx = v.x - __uint_as_float(hp0 << 16);
        float ly = v.y - __uint_as_float(hp0 & 0xFFFF0000u);
        float lz = v.z - __uint_as_float(hp1 << 16);
        float lw = v.w - __uint_as_float(hp1 & 0xFFFF0000u);
        *(uint2*)&xh[(size_t)i * 4] = make_uint2(hp0, hp1);
        *(uint2*)&xl[(size_t)i * 4] = make_uint2(cvt2(lx, ly), cvt2(lz, lw));
    }
}

// ---------------- CSR build: hist + 3-phase grid scan + scatter ----------------
__global__ void hist_kernel(const int* __restrict__ dst, int* __restrict__ counts, int E)
{
    int i = blockIdx.x * blockDim.x + threadIdx.x;
    if (i < E) atomicAdd(&counts[dst[i]], 1);
}

__global__ void scan_part(const int* __restrict__ counts, int* __restrict__ bsum, int N)
{
    __shared__ int wtot[8];
    int t = threadIdx.x, wid = t >> 5, lane = t & 31;
    int s = 0;
#pragma unroll
    for (int i = 0; i < 8; ++i) {
        int idx = blockIdx.x * 2048 + t * 8 + i;
        if (idx < N) s += counts[idx];
    }
#pragma unroll
    for (int d = 16; d; d >>= 1) s += __shfl_xor_sync(0xFFFFFFFFu, s, d);
    if (lane == 0) wtot[wid] = s;
    __syncthreads();
    if (t == 0) {
        int tot = 0;
#pragma unroll
        for (int i = 0; i < 8; ++i) tot += wtot[i];
        bsum[blockIdx.x] = tot;
    }
}
__global__ void scan_mid(int* __restrict__ bsum, int nb, int* __restrict__ off, int N, int E)
{
    int lane = threadIdx.x;
    int v = (lane < nb) ? bsum[lane] : 0;
    int orig = v;
#pragma unroll
    for (int d = 1; d < 32; d <<= 1) {
        int u = __shfl_up_sync(0xFFFFFFFFu, v, d);
        if (lane >= d) v += u;
    }
    if (lane < nb) bsum[lane] = v - orig;
    if (lane == 0) off[N] = E;
}
__global__ void scan_final(const int* __restrict__ counts, const int* __restrict__ bsum,
                           int* __restrict__ off, int* __restrict__ cursor, int N)
{
    __shared__ int wtot[8];
    int t = threadIdx.x, wid = t >> 5, lane = t & 31;
    int base = blockIdx.x * 2048 + t * 8;
    int c[8];
    int s = 0;
#pragma unroll
    for (int i = 0; i < 8; ++i) {
        int idx = base + i;
        c[i] = (idx < N) ? counts[idx] : 0;
        s += c[i];
    }
    int incl = s;
#pragma unroll
    for (int d = 1; d < 32; d <<= 1) {
        int u = __shfl_up_sync(0xFFFFFFFFu, incl, d);
        if (lane >= d) incl += u;
    }
    if (lane == 31) wtot[wid] = incl;
    __syncthreads();
    int wbase = 0;
#pragma unroll
    for (int i = 0; i < 8; ++i) wbase += (i < wid) ? wtot[i] : 0;
    int run = bsum[blockIdx.x] + wbase + (incl - s);
#pragma unroll
    for (int i = 0; i < 8; ++i) {
        int idx = base + i;
        if (idx < N) { off[idx] = run; cursor[idx] = run; }
        run += c[i];
    }
}

__global__ void scatter_kernel(const int* __restrict__ dst, int* __restrict__ cursor,
                               int* __restrict__ elist, int E)
{
    int i = blockIdx.x * blockDim.x + threadIdx.x;
    if (i < E) {
        int p = atomicAdd(&cursor[dst[i]], 1);
        elist[p] = i;
    }
}

// ---------------- fused per-node sweep with depth-2 index prefetch -------------
__global__ void aggregate(const float* __restrict__ e, const float* __restrict__ v,
                          const float* __restrict__ q, const float* __restrict__ k,
                          const int* __restrict__ src,
                          const int* __restrict__ off, const int* __restrict__ elist,
                          float* __restrict__ escore,
                          float* __restrict__ o, float* __restrict__ out2, int N)
{
    int w = (blockIdx.x * blockDim.x + threadIdx.x) >> 5;
    int lane = threadIdx.x & 31;
    if (w >= N) return;
    int hl = lane >> 2;
    int beg = off[w], end = off[w + 1];
    float4 qv = *(const float4*)&q[(size_t)w * 128 + (lane << 2)];
    float zl = 0.f;
    float ax = 0.f, ay = 0.f, az = 0.f, aw = 0.f;

    int eid = 0, s = 0;
    if (beg < end) { eid = elist[beg]; s = src[eid]; }
    for (int idx = beg; idx < end; ++idx) {
        // issue current row loads immediately (indices already resolved)
        float4 ev = *(const float4*)&e[(size_t)eid * 128 + (lane << 2)];
        float4 kv = *(const float4*)&k[(size_t)s * 128 + (lane << 2)];
        float4 vv = *(const float4*)&v[(size_t)s * 128 + (lane << 2)];
        int cur_eid = eid;
        // resolve next indices while the above loads are in flight
        if (idx + 1 < end) {
            int ne = elist[idx + 1];
            eid = ne;
            s = src[ne];
        }
        float p = qv.x * (kv.x + ev.x) + qv.y * (kv.y + ev.y)
                + qv.z * (kv.z + ev.z) + qv.w * (kv.w + ev.w);
        p += __shfl_xor_sync(0xFFFFFFFFu, p, 1);
        p += __shfl_xor_sync(0xFFFFFFFFu, p, 2);
        float esc = expf(p);
        zl += esc;
        ax += esc * (ev.x + vv.x);
        ay += esc * (ev.y + vv.y);
        az += esc * (ev.z + vv.z);
        aw += esc * (ev.w + vv.w);
        if ((lane & 3) == 0) escore[(size_t)cur_eid * 8 + hl] = esc;
    }

    float sc = 0.25f / (1e-8f + zl);
    float4 ov; ov.x = ax * sc; ov.y = ay * sc; ov.z = az * sc; ov.w = aw * sc;
    *(float4*)&o[(size_t)w * 128 + (lane << 2)] = ov;
    if ((lane & 3) == 0) {
        for (int idx = beg; idx < end; ++idx) {
            int e2 = elist[idx];
            out2[(size_t)e2 * 8 + hl] = sc * escore[(size_t)e2 * 8 + hl];
        }
    }
}

// ---------------- launch ---------------------------------------------------------
extern "C" void kernel_launch(void* const* d_in, const int* in_sizes, int n_in,
                              void* d_out, int out_size)
{
    const float* x   = (const float*)d_in[0];
    const float* y   = (const float*)d_in[1];
    const int*   src = (const int*)d_in[2];
    const int*   dst = (const int*)d_in[3];
    const float* Wq  = (const float*)d_in[4];
    const float* bq  = (const float*)d_in[5];
    const float* Wk  = (const float*)d_in[6];
    const float* bk  = (const float*)d_in[7];
    const float* Wv  = (const float*)d_in[8];
    const float* bv  = (const float*)d_in[9];
    const float* We  = (const float*)d_in[10];
    const float* be  = (const float*)d_in[11];
    const float* Wr  = (const float*)d_in[12];
    const float* br  = (const float*)d_in[13];
    const float* Wg  = (const float*)d_in[14];
    const float* bg  = (const float*)d_in[15];
    const float* lng = (const float*)d_in[16];
    const float* lnb = (const float*)d_in[17];

    const int N = in_sizes[0] / 128;
    const int E = in_sizes[2];

    float *q, *k, *v, *r, *o, *e, *escore;
    __nv_bfloat16 *wt, *xh, *xl;
    int *counts, *off, *cursor, *elist, *bsum;
    void* p;
    cudaGetSymbolAddress(&p, g_q);      q = (float*)p;
    cudaGetSymbolAddress(&p, g_k);      k = (float*)p;
    cudaGetSymbolAddress(&p, g_v);      v = (float*)p;
    cudaGetSymbolAddress(&p, g_r);      r = (float*)p;
    cudaGetSymbolAddress(&p, g_o);      o = (float*)p;
    cudaGetSymbolAddress(&p, g_e);      e = (float*)p;
    cudaGetSymbolAddress(&p, g_escore); escore = (float*)p;
    cudaGetSymbolAddress(&p, g_wt);     wt = (__nv_bfloat16*)p;
    cudaGetSymbolAddress(&p, g_xh);     xh = (__nv_bfloat16*)p;
    cudaGetSymbolAddress(&p, g_xl);     xl = (__nv_bfloat16*)p;
    cudaGetSymbolAddress(&p, g_counts); counts = (int*)p;
    cudaGetSymbolAddress(&p, g_off);    off = (int*)p;
    cudaGetSymbolAddress(&p, g_cursor); cursor = (int*)p;
    cudaGetSymbolAddress(&p, g_elist);  elist = (int*)p;
    cudaGetSymbolAddress(&p, g_bsum);   bsum = (int*)p;

    cudaFuncSetAttribute(tc_gemm,   cudaFuncAttributeMaxDynamicSharedMemorySize, SMEM_EP);
    cudaFuncSetAttribute(qkvr_gemm, cudaFuncAttributeMaxDynamicSharedMemorySize, SMEM_G);
    cudaFuncSetAttribute(gate_ln,   cudaFuncAttributeMaxDynamicSharedMemorySize, SMEM_G);

    float* out  = (float*)d_out;
    float* out2 = out + (size_t)N * 128;

    __nv_bfloat16* we_h = wt + 4 * 32768; __nv_bfloat16* we_l = we_h + 16384;
    __nv_bfloat16* w1_h = wt + 5 * 32768;
    __nv_bfloat16* w2_h = wt + 6 * 32768;

    const int gN = (N + 63) / 64;
    const int nb = (N + 2047) / 2048;
    const int numTiles = (E + 127) / 128;
    const int gPersist = numTiles < 148 ? numTiles : 148;

    static cudaStream_t s1 = nullptr, s2 = nullptr;
    static cudaEvent_t evFork = nullptr, evJ1 = nullptr, evJ2 = nullptr;
    if (s1 == nullptr) {
        cudaStreamCreateWithFlags(&s1, cudaStreamNonBlocking);
        cudaStreamCreateWithFlags(&s2, cudaStreamNonBlocking);
        cudaEventCreateWithFlags(&evFork, cudaEventDisableTiming);
        cudaEventCreateWithFlags(&evJ1,   cudaEventDisableTiming);
        cudaEventCreateWithFlags(&evJ2,   cudaEventDisableTiming);
    }

    prep_all<<<448, 256>>>(Wq, Wk, Wv, Wr, We, Wg, wt);
    cudaEventRecord(evFork, 0);
    cudaStreamWaitEvent(s1, evFork, 0);
    cudaStreamWaitEvent(s2, evFork, 0);

    tc_gemm<<<gPersist, 256, SMEM_EP, 0>>>(y, we_h, we_l, be, e, E);

    prep_x<<<(N * 32 + 255) / 256, 256, 0, s1>>>(x, xh, xl, N * 32);
    qkvr_gemm<<<gN, 256, SMEM_G, s1>>>(xh, xl, wt, bq, bk, bv, br, q, k, v, r, N);

    cudaMemsetAsync(counts, 0, (size_t)N * sizeof(int), s2);
    hist_kernel<<<(E + 255) / 256, 256, 0, s2>>>(dst, counts, E);
    scan_part<<<nb, 256, 0, s2>>>(counts, bsum, N);
    scan_mid<<<1, 32, 0, s2>>>(bsum, nb, off, N, E);
    scan_final<<<nb, 256, 0, s2>>>(counts, bsum, off, cursor, N);
    scatter_kernel<<<(E + 255) / 256, 256, 0, s2>>>(dst, cursor, elist, E);

    cudaEventRecord(evJ1, s1);
    cudaEventRecord(evJ2, s2);
    cudaStreamWaitEvent(0, evJ1, 0);
    cudaStreamWaitEvent(0, evJ2, 0);

    aggregate<<<(N + 7) / 8, 256>>>(e, v, q, k, src, off, elist, escore, o, out2, N);
    gate_ln<<<gN, 256, SMEM_G>>>(o, r, w1_h, w2_h, bg, lng, lnb, out, N);
}